// round 15
// baseline (speedup 1.0000x reference)
#include <cuda_runtime.h>

#define B_ 4
#define C_ 256
#define H_ 64
#define W_ 64
#define COMP_ 64
#define HW_ (H_*W_)   // 4096
#define K2_ 25
#define S2_ 4

// Scratch (no allocations allowed): activation after compress+BN+SiLU, and softmaxed masks
__device__ float g_act[B_*COMP_*HW_];                 // [b][co][h][w]   4 MB
__device__ float g_mask[B_*K2_*S2_*HW_];              // [b][k2][s2][h][w] 6.5 MB

// ---------------------------------------------------------------------------
// Kernel A: 1x1 compression conv + BatchNorm(eval) + SiLU
// 1 thread = 1 pixel, 64 fp32 accumulators. w_comp transposed into smem
// (padded rows for conflict-free float4 reads, broadcast across the warp).
// ---------------------------------------------------------------------------
__global__ __launch_bounds__(256) void kA(const float* __restrict__ x,
                                          const float* __restrict__ w_comp,
                                          const float* __restrict__ gamma_,
                                          const float* __restrict__ beta_,
                                          const float* __restrict__ mean_,
                                          const float* __restrict__ var_) {
    __shared__ float ws[128][68];    // [c][o], row padded to 68 (16B aligned, banked)
    __shared__ float s_inv[64], s_beta[64], s_mean[64];
    int tid = threadIdx.x;
    int pix = blockIdx.x * 256 + tid;   // global pixel id across batch
    int b = pix >> 12;                  // /4096
    int p = pix & 4095;
    if (tid < 64) {
        s_inv[tid]  = gamma_[tid] * rsqrtf(var_[tid] + 1e-5f);
        s_beta[tid] = beta_[tid];
        s_mean[tid] = mean_[tid];
    }
    float acc[64];
    #pragma unroll
    for (int o = 0; o < 64; o++) acc[o] = 0.f;

    for (int cc = 0; cc < 2; cc++) {
        int c0 = cc * 128;
        __syncthreads();
        // coalesced load of w chunk, transposed store: ws[c][o] = w_comp[o][c0+c]
        for (int i = tid; i < 128 * 64; i += 256) {
            int o = i >> 7;           // 0..63
            int c = i & 127;          // 0..127 (fastest -> coalesced global read)
            ws[c][o] = w_comp[o * C_ + c0 + c];
        }
        __syncthreads();
        const float* xb = x + ((size_t)b * C_ + c0) * HW_ + p;
        #pragma unroll 4
        for (int c = 0; c < 128; c++) {
            float xv = xb[(size_t)c * HW_];
            const float4* wr = (const float4*)ws[c];
            #pragma unroll
            for (int q = 0; q < 16; q++) {
                float4 w4 = wr[q];
                acc[q*4+0] += xv * w4.x;
                acc[q*4+1] += xv * w4.y;
                acc[q*4+2] += xv * w4.z;
                acc[q*4+3] += xv * w4.w;
            }
        }
    }
    float* ab = g_act + (size_t)b * COMP_ * HW_ + p;
    #pragma unroll
    for (int o = 0; o < 64; o++) {
        float bn = (acc[o] - s_mean[o]) * s_inv[o] + s_beta[o];
        float a = bn / (1.f + __expf(-bn));   // SiLU
        ab[(size_t)o * HW_] = a;
    }
}

// ---------------------------------------------------------------------------
// Kernel B: 3x3 encoder conv -> 25-way softmax per sub-pixel position.
// Split by s2 (softmax is independent per s2): each block computes 25 of the
// 100 output channels for a 16x16 pixel tile. act tile (+1 halo) and w_enc
// chunk live in smem; w rows are k2-contiguous for float4 broadcast LDS.
// grid: (16 tiles, 4 s2, 4 b) = 256 blocks, 256 threads.
// ---------------------------------------------------------------------------
__global__ __launch_bounds__(256) void kB(const float* __restrict__ w_enc) {
    __shared__ float as_[8][18][18];     // 8 channels x (16+2)^2
    __shared__ float ws_[8][9][28];      // [co][tap][k2], row padded to 28 (16B aligned)
    int tid = threadIdx.x;
    int tx = tid & 15, ty = tid >> 4;
    int tile = blockIdx.x;
    int ty0 = (tile >> 2) << 4, tx0 = (tile & 3) << 4;
    int s2 = blockIdx.y, b = blockIdx.z;

    float acc[25];
    #pragma unroll
    for (int k = 0; k < 25; k++) acc[k] = 0.f;

    for (int c0 = 0; c0 < COMP_; c0 += 8) {
        __syncthreads();
        // load activation chunk with halo (zero pad at image border)
        for (int i = tid; i < 8 * 18 * 18; i += 256) {
            int co = i / 324;
            int r  = (i % 324) / 18;
            int cx = i % 18;
            int gy = ty0 + r - 1, gx = tx0 + cx - 1;
            float v = 0.f;
            if ((unsigned)gy < 64u && (unsigned)gx < 64u)
                v = g_act[((size_t)b * COMP_ + c0 + co) * HW_ + gy * 64 + gx];
            as_[co][r][cx] = v;
        }
        // load filter chunk: ws_[co][tap][k2] = w_enc[(k2*4+s2)][c0+co][tap]
        for (int i = tid; i < 8 * 9 * 25; i += 256) {
            int co = i / 225;
            int rem = i % 225;
            int tap = rem / 25;
            int k2 = rem % 25;
            ws_[co][tap][k2] = w_enc[(((size_t)(k2 * 4 + s2)) * COMP_ + c0 + co) * 9 + tap];
        }
        __syncthreads();

        for (int co = 0; co < 8; co++) {
            #pragma unroll
            for (int tap = 0; tap < 9; tap++) {
                int kh = tap / 3, kw = tap % 3;
                float a = as_[co][ty + kh][tx + kw];
                const float4* wr = (const float4*)&ws_[co][tap][0];
                #pragma unroll
                for (int q = 0; q < 6; q++) {
                    float4 w4 = wr[q];
                    acc[q*4+0] += a * w4.x;
                    acc[q*4+1] += a * w4.y;
                    acc[q*4+2] += a * w4.z;
                    acc[q*4+3] += a * w4.w;
                }
                acc[24] += a * ws_[co][tap][24];
            }
        }
    }

    // softmax over the 25 k_up*k_up logits
    float m = acc[0];
    #pragma unroll
    for (int k = 1; k < 25; k++) m = fmaxf(m, acc[k]);
    float sum = 0.f;
    #pragma unroll
    for (int k = 0; k < 25; k++) { acc[k] = __expf(acc[k] - m); sum += acc[k]; }
    float rinv = 1.f / sum;
    int p = (ty0 + ty) * 64 + tx0 + tx;
    #pragma unroll
    for (int k = 0; k < 25; k++)
        g_mask[(((size_t)b * K2_ + k) * S2_ + s2) * HW_ + p] = acc[k] * rinv;
}

// ---------------------------------------------------------------------------
// Kernel C: content-aware reassembly. Each thread owns one pixel and keeps
// its 100 mask weights in registers; per channel a 20x20 (tile+2 halo) x-tile
// is staged in smem; 4 upsampled outputs per channel, float2 stores.
// grid: (16 tiles, 8 channel groups of 32, 4 b) = 512 blocks, 256 threads.
// ---------------------------------------------------------------------------
__global__ __launch_bounds__(256) void kC(const float* __restrict__ x,
                                          float* __restrict__ out) {
    __shared__ float xs[20][20];
    int tid = threadIdx.x;
    int tx = tid & 15, ty = tid >> 4;
    int tile = blockIdx.x;
    int ty0 = (tile >> 2) << 4, tx0 = (tile & 3) << 4;
    int cg = blockIdx.y, b = blockIdx.z;
    int p = (ty0 + ty) * 64 + tx0 + tx;

    float mk[100];
    #pragma unroll
    for (int k = 0; k < 25; k++)
        #pragma unroll
        for (int s = 0; s < 4; s++)
            mk[k*4+s] = g_mask[(((size_t)b * K2_ + k) * S2_ + s) * HW_ + p];

    for (int ci = 0; ci < 32; ci++) {
        int c = cg * 32 + ci;
        __syncthreads();
        for (int i = tid; i < 400; i += 256) {
            int r = i / 20, cc = i % 20;
            int gy = ty0 + r - 2, gx = tx0 + cc - 2;
            float v = 0.f;
            if ((unsigned)gy < 64u && (unsigned)gx < 64u)
                v = x[((size_t)b * C_ + c) * HW_ + gy * 64 + gx];
            xs[r][cc] = v;
        }
        __syncthreads();
        float a0 = 0.f, a1 = 0.f, a2 = 0.f, a3 = 0.f;
        #pragma unroll
        for (int dy = 0; dy < 5; dy++) {
            #pragma unroll
            for (int dx = 0; dx < 5; dx++) {
                float xv = xs[ty + dy][tx + dx];
                int k = dy * 5 + dx;
                a0 += mk[k*4+0] * xv;
                a1 += mk[k*4+1] * xv;
                a2 += mk[k*4+2] * xv;
                a3 += mk[k*4+3] * xv;
            }
        }
        // s2 -> (s0,s1): output pixel (2i+s0, 2j+s1)
        float* ob = out + (((size_t)b * C_ + c) * 128 + (size_t)(ty0 + ty) * 2) * 128
                        + (size_t)(tx0 + tx) * 2;
        *(float2*)(ob)       = make_float2(a0, a1);
        *(float2*)(ob + 128) = make_float2(a2, a3);
    }
}

// ---------------------------------------------------------------------------
extern "C" void kernel_launch(void* const* d_in, const int* in_sizes, int n_in,
                              void* d_out, int out_size) {
    const float* x      = (const float*)d_in[0];
    const float* w_comp = (const float*)d_in[1];
    const float* gamma_ = (const float*)d_in[2];
    const float* beta_  = (const float*)d_in[3];
    const float* mean_  = (const float*)d_in[4];
    const float* var_   = (const float*)d_in[5];
    const float* w_enc  = (const float*)d_in[6];
    float* out = (float*)d_out;

    kA<<<64, 256>>>(x, w_comp, gamma_, beta_, mean_, var_);
    kB<<<dim3(16, 4, 4), 256>>>(w_enc);
    kC<<<dim3(16, 8, 4), 256>>>(x, out);
}

// round 16
// speedup vs baseline: 1.0070x; 1.0070x over previous
#include <cuda_runtime.h>

#define B_ 4
#define C_ 256
#define H_ 64
#define W_ 64
#define COMP_ 64
#define HW_ (H_*W_)   // 4096
#define K2_ 25
#define S2_ 4

// Scratch (no allocations allowed): activation after compress+BN+SiLU, and softmaxed masks
__device__ float g_act[B_*COMP_*HW_];                 // [b][co][h][w]   4 MB
__device__ float g_mask[B_*K2_*S2_*HW_];              // [b][k2][s2][h][w] 6.5 MB

// ---------------------------------------------------------------------------
// Kernel A: 1x1 compression conv + BatchNorm(eval) + SiLU
// 1 thread = 1 pixel, 64 fp32 accumulators. w_comp transposed into smem
// (padded rows for conflict-free float4 reads, broadcast across the warp).
// ---------------------------------------------------------------------------
__global__ __launch_bounds__(256) void kA(const float* __restrict__ x,
                                          const float* __restrict__ w_comp,
                                          const float* __restrict__ gamma_,
                                          const float* __restrict__ beta_,
                                          const float* __restrict__ mean_,
                                          const float* __restrict__ var_) {
    __shared__ float ws[128][68];    // [c][o], row padded to 68 (16B aligned, banked)
    __shared__ float s_inv[64], s_beta[64], s_mean[64];
    int tid = threadIdx.x;
    int pix = blockIdx.x * 256 + tid;   // global pixel id across batch
    int b = pix >> 12;                  // /4096
    int p = pix & 4095;
    if (tid < 64) {
        s_inv[tid]  = gamma_[tid] * rsqrtf(var_[tid] + 1e-5f);
        s_beta[tid] = beta_[tid];
        s_mean[tid] = mean_[tid];
    }
    float acc[64];
    #pragma unroll
    for (int o = 0; o < 64; o++) acc[o] = 0.f;

    for (int cc = 0; cc < 2; cc++) {
        int c0 = cc * 128;
        __syncthreads();
        // coalesced load of w chunk, transposed store: ws[c][o] = w_comp[o][c0+c]
        for (int i = tid; i < 128 * 64; i += 256) {
            int o = i >> 7;           // 0..63
            int c = i & 127;          // 0..127 (fastest -> coalesced global read)
            ws[c][o] = w_comp[o * C_ + c0 + c];
        }
        __syncthreads();
        const float* xb = x + ((size_t)b * C_ + c0) * HW_ + p;
        #pragma unroll 4
        for (int c = 0; c < 128; c++) {
            float xv = xb[(size_t)c * HW_];
            const float4* wr = (const float4*)ws[c];
            #pragma unroll
            for (int q = 0; q < 16; q++) {
                float4 w4 = wr[q];
                acc[q*4+0] += xv * w4.x;
                acc[q*4+1] += xv * w4.y;
                acc[q*4+2] += xv * w4.z;
                acc[q*4+3] += xv * w4.w;
            }
        }
    }
    float* ab = g_act + (size_t)b * COMP_ * HW_ + p;
    #pragma unroll
    for (int o = 0; o < 64; o++) {
        float bn = (acc[o] - s_mean[o]) * s_inv[o] + s_beta[o];
        float a = bn / (1.f + __expf(-bn));   // SiLU
        ab[(size_t)o * HW_] = a;
    }
}

// ---------------------------------------------------------------------------
// Kernel B: 3x3 encoder conv -> 25-way softmax per sub-pixel position.
// Split by s2 (softmax is independent per s2): each block computes 25 of the
// 100 output channels for a 16x16 pixel tile. act tile (+1 halo) and w_enc
// chunk live in smem; w rows are k2-contiguous for float4 broadcast LDS.
// grid: (16 tiles, 4 s2, 4 b) = 256 blocks, 256 threads.
// ---------------------------------------------------------------------------
__global__ __launch_bounds__(256) void kB(const float* __restrict__ w_enc) {
    __shared__ float as_[8][18][18];     // 8 channels x (16+2)^2
    __shared__ float ws_[8][9][28];      // [co][tap][k2], row padded to 28 (16B aligned)
    int tid = threadIdx.x;
    int tx = tid & 15, ty = tid >> 4;
    int tile = blockIdx.x;
    int ty0 = (tile >> 2) << 4, tx0 = (tile & 3) << 4;
    int s2 = blockIdx.y, b = blockIdx.z;

    float acc[25];
    #pragma unroll
    for (int k = 0; k < 25; k++) acc[k] = 0.f;

    for (int c0 = 0; c0 < COMP_; c0 += 8) {
        __syncthreads();
        // load activation chunk with halo (zero pad at image border)
        for (int i = tid; i < 8 * 18 * 18; i += 256) {
            int co = i / 324;
            int r  = (i % 324) / 18;
            int cx = i % 18;
            int gy = ty0 + r - 1, gx = tx0 + cx - 1;
            float v = 0.f;
            if ((unsigned)gy < 64u && (unsigned)gx < 64u)
                v = g_act[((size_t)b * COMP_ + c0 + co) * HW_ + gy * 64 + gx];
            as_[co][r][cx] = v;
        }
        // load filter chunk: ws_[co][tap][k2] = w_enc[(k2*4+s2)][c0+co][tap]
        for (int i = tid; i < 8 * 9 * 25; i += 256) {
            int co = i / 225;
            int rem = i % 225;
            int tap = rem / 25;
            int k2 = rem % 25;
            ws_[co][tap][k2] = w_enc[(((size_t)(k2 * 4 + s2)) * COMP_ + c0 + co) * 9 + tap];
        }
        __syncthreads();

        for (int co = 0; co < 8; co++) {
            #pragma unroll
            for (int tap = 0; tap < 9; tap++) {
                int kh = tap / 3, kw = tap % 3;
                float a = as_[co][ty + kh][tx + kw];
                const float4* wr = (const float4*)&ws_[co][tap][0];
                #pragma unroll
                for (int q = 0; q < 6; q++) {
                    float4 w4 = wr[q];
                    acc[q*4+0] += a * w4.x;
                    acc[q*4+1] += a * w4.y;
                    acc[q*4+2] += a * w4.z;
                    acc[q*4+3] += a * w4.w;
                }
                acc[24] += a * ws_[co][tap][24];
            }
        }
    }

    // softmax over the 25 k_up*k_up logits
    float m = acc[0];
    #pragma unroll
    for (int k = 1; k < 25; k++) m = fmaxf(m, acc[k]);
    float sum = 0.f;
    #pragma unroll
    for (int k = 0; k < 25; k++) { acc[k] = __expf(acc[k] - m); sum += acc[k]; }
    float rinv = 1.f / sum;
    int p = (ty0 + ty) * 64 + tx0 + tx;
    #pragma unroll
    for (int k = 0; k < 25; k++)
        g_mask[(((size_t)b * K2_ + k) * S2_ + s2) * HW_ + p] = acc[k] * rinv;
}

// ---------------------------------------------------------------------------
// Kernel C: content-aware reassembly. Each thread owns one pixel and keeps
// its 100 mask weights in registers; per channel a 20x20 (tile+2 halo) x-tile
// is staged in smem; 4 upsampled outputs per channel, float2 stores.
// grid: (16 tiles, 8 channel groups of 32, 4 b) = 512 blocks, 256 threads.
// ---------------------------------------------------------------------------
__global__ __launch_bounds__(256) void kC(const float* __restrict__ x,
                                          float* __restrict__ out) {
    __shared__ float xs[20][20];
    int tid = threadIdx.x;
    int tx = tid & 15, ty = tid >> 4;
    int tile = blockIdx.x;
    int ty0 = (tile >> 2) << 4, tx0 = (tile & 3) << 4;
    int cg = blockIdx.y, b = blockIdx.z;
    int p = (ty0 + ty) * 64 + tx0 + tx;

    float mk[100];
    #pragma unroll
    for (int k = 0; k < 25; k++)
        #pragma unroll
        for (int s = 0; s < 4; s++)
            mk[k*4+s] = g_mask[(((size_t)b * K2_ + k) * S2_ + s) * HW_ + p];

    for (int ci = 0; ci < 32; ci++) {
        int c = cg * 32 + ci;
        __syncthreads();
        for (int i = tid; i < 400; i += 256) {
            int r = i / 20, cc = i % 20;
            int gy = ty0 + r - 2, gx = tx0 + cc - 2;
            float v = 0.f;
            if ((unsigned)gy < 64u && (unsigned)gx < 64u)
                v = x[((size_t)b * C_ + c) * HW_ + gy * 64 + gx];
            xs[r][cc] = v;
        }
        __syncthreads();
        float a0 = 0.f, a1 = 0.f, a2 = 0.f, a3 = 0.f;
        #pragma unroll
        for (int dy = 0; dy < 5; dy++) {
            #pragma unroll
            for (int dx = 0; dx < 5; dx++) {
                float xv = xs[ty + dy][tx + dx];
                int k = dy * 5 + dx;
                a0 += mk[k*4+0] * xv;
                a1 += mk[k*4+1] * xv;
                a2 += mk[k*4+2] * xv;
                a3 += mk[k*4+3] * xv;
            }
        }
        // s2 -> (s0,s1): output pixel (2i+s0, 2j+s1)
        float* ob = out + (((size_t)b * C_ + c) * 128 + (size_t)(ty0 + ty) * 2) * 128
                        + (size_t)(tx0 + tx) * 2;
        *(float2*)(ob)       = make_float2(a0, a1);
        *(float2*)(ob + 128) = make_float2(a2, a3);
    }
}

// ---------------------------------------------------------------------------
extern "C" void kernel_launch(void* const* d_in, const int* in_sizes, int n_in,
                              void* d_out, int out_size) {
    const float* x      = (const float*)d_in[0];
    const float* w_comp = (const float*)d_in[1];
    const float* gamma_ = (const float*)d_in[2];
    const float* beta_  = (const float*)d_in[3];
    const float* mean_  = (const float*)d_in[4];
    const float* var_   = (const float*)d_in[5];
    const float* w_enc  = (const float*)d_in[6];
    float* out = (float*)d_out;

    kA<<<64, 256>>>(x, w_comp, gamma_, beta_, mean_, var_);
    kB<<<dim3(16, 4, 4), 256>>>(w_enc);
    kC<<<dim3(16, 8, 4), 256>>>(x, out);
}

// round 17
// speedup vs baseline: 1.0103x; 1.0033x over previous
#include <cuda_runtime.h>

#define B_ 4
#define C_ 256
#define H_ 64
#define W_ 64
#define COMP_ 64
#define HW_ (H_*W_)   // 4096
#define K2_ 25
#define S2_ 4

// Scratch (no allocations allowed): activation after compress+BN+SiLU, and softmaxed masks
__device__ float g_act[B_*COMP_*HW_];                 // [b][co][h][w]   4 MB
__device__ float g_mask[B_*K2_*S2_*HW_];              // [b][k2][s2][h][w] 6.5 MB

// ---------------------------------------------------------------------------
// Kernel A: 1x1 compression conv + BatchNorm(eval) + SiLU
// 1 thread = 1 pixel, 64 fp32 accumulators. w_comp transposed into smem
// (padded rows for conflict-free float4 reads, broadcast across the warp).
// ---------------------------------------------------------------------------
__global__ __launch_bounds__(256) void kA(const float* __restrict__ x,
                                          const float* __restrict__ w_comp,
                                          const float* __restrict__ gamma_,
                                          const float* __restrict__ beta_,
                                          const float* __restrict__ mean_,
                                          const float* __restrict__ var_) {
    __shared__ float ws[128][68];    // [c][o], row padded to 68 (16B aligned, banked)
    __shared__ float s_inv[64], s_beta[64], s_mean[64];
    int tid = threadIdx.x;
    int pix = blockIdx.x * 256 + tid;   // global pixel id across batch
    int b = pix >> 12;                  // /4096
    int p = pix & 4095;
    if (tid < 64) {
        s_inv[tid]  = gamma_[tid] * rsqrtf(var_[tid] + 1e-5f);
        s_beta[tid] = beta_[tid];
        s_mean[tid] = mean_[tid];
    }
    float acc[64];
    #pragma unroll
    for (int o = 0; o < 64; o++) acc[o] = 0.f;

    for (int cc = 0; cc < 2; cc++) {
        int c0 = cc * 128;
        __syncthreads();
        // coalesced load of w chunk, transposed store: ws[c][o] = w_comp[o][c0+c]
        for (int i = tid; i < 128 * 64; i += 256) {
            int o = i >> 7;           // 0..63
            int c = i & 127;          // 0..127 (fastest -> coalesced global read)
            ws[c][o] = w_comp[o * C_ + c0 + c];
        }
        __syncthreads();
        const float* xb = x + ((size_t)b * C_ + c0) * HW_ + p;
        #pragma unroll 4
        for (int c = 0; c < 128; c++) {
            float xv = xb[(size_t)c * HW_];
            const float4* wr = (const float4*)ws[c];
            #pragma unroll
            for (int q = 0; q < 16; q++) {
                float4 w4 = wr[q];
                acc[q*4+0] += xv * w4.x;
                acc[q*4+1] += xv * w4.y;
                acc[q*4+2] += xv * w4.z;
                acc[q*4+3] += xv * w4.w;
            }
        }
    }
    float* ab = g_act + (size_t)b * COMP_ * HW_ + p;
    #pragma unroll
    for (int o = 0; o < 64; o++) {
        float bn = (acc[o] - s_mean[o]) * s_inv[o] + s_beta[o];
        float a = bn / (1.f + __expf(-bn));   // SiLU
        ab[(size_t)o * HW_] = a;
    }
}

// ---------------------------------------------------------------------------
// Kernel B: 3x3 encoder conv -> 25-way softmax per sub-pixel position.
// Split by s2 (softmax is independent per s2): each block computes 25 of the
// 100 output channels for a 16x16 pixel tile. act tile (+1 halo) and w_enc
// chunk live in smem; w rows are k2-contiguous for float4 broadcast LDS.
// grid: (16 tiles, 4 s2, 4 b) = 256 blocks, 256 threads.
// ---------------------------------------------------------------------------
__global__ __launch_bounds__(256) void kB(const float* __restrict__ w_enc) {
    __shared__ float as_[8][18][18];     // 8 channels x (16+2)^2
    __shared__ float ws_[8][9][28];      // [co][tap][k2], row padded to 28 (16B aligned)
    int tid = threadIdx.x;
    int tx = tid & 15, ty = tid >> 4;
    int tile = blockIdx.x;
    int ty0 = (tile >> 2) << 4, tx0 = (tile & 3) << 4;
    int s2 = blockIdx.y, b = blockIdx.z;

    float acc[25];
    #pragma unroll
    for (int k = 0; k < 25; k++) acc[k] = 0.f;

    for (int c0 = 0; c0 < COMP_; c0 += 8) {
        __syncthreads();
        // load activation chunk with halo (zero pad at image border)
        for (int i = tid; i < 8 * 18 * 18; i += 256) {
            int co = i / 324;
            int r  = (i % 324) / 18;
            int cx = i % 18;
            int gy = ty0 + r - 1, gx = tx0 + cx - 1;
            float v = 0.f;
            if ((unsigned)gy < 64u && (unsigned)gx < 64u)
                v = g_act[((size_t)b * COMP_ + c0 + co) * HW_ + gy * 64 + gx];
            as_[co][r][cx] = v;
        }
        // load filter chunk: ws_[co][tap][k2] = w_enc[(k2*4+s2)][c0+co][tap]
        for (int i = tid; i < 8 * 9 * 25; i += 256) {
            int co = i / 225;
            int rem = i % 225;
            int tap = rem / 25;
            int k2 = rem % 25;
            ws_[co][tap][k2] = w_enc[(((size_t)(k2 * 4 + s2)) * COMP_ + c0 + co) * 9 + tap];
        }
        __syncthreads();

        for (int co = 0; co < 8; co++) {
            #pragma unroll
            for (int tap = 0; tap < 9; tap++) {
                int kh = tap / 3, kw = tap % 3;
                float a = as_[co][ty + kh][tx + kw];
                const float4* wr = (const float4*)&ws_[co][tap][0];
                #pragma unroll
                for (int q = 0; q < 6; q++) {
                    float4 w4 = wr[q];
                    acc[q*4+0] += a * w4.x;
                    acc[q*4+1] += a * w4.y;
                    acc[q*4+2] += a * w4.z;
                    acc[q*4+3] += a * w4.w;
                }
                acc[24] += a * ws_[co][tap][24];
            }
        }
    }

    // softmax over the 25 k_up*k_up logits
    float m = acc[0];
    #pragma unroll
    for (int k = 1; k < 25; k++) m = fmaxf(m, acc[k]);
    float sum = 0.f;
    #pragma unroll
    for (int k = 0; k < 25; k++) { acc[k] = __expf(acc[k] - m); sum += acc[k]; }
    float rinv = 1.f / sum;
    int p = (ty0 + ty) * 64 + tx0 + tx;
    #pragma unroll
    for (int k = 0; k < 25; k++)
        g_mask[(((size_t)b * K2_ + k) * S2_ + s2) * HW_ + p] = acc[k] * rinv;
}

// ---------------------------------------------------------------------------
// Kernel C: content-aware reassembly. Each thread owns one pixel and keeps
// its 100 mask weights in registers; per channel a 20x20 (tile+2 halo) x-tile
// is staged in smem; 4 upsampled outputs per channel, float2 stores.
// grid: (16 tiles, 8 channel groups of 32, 4 b) = 512 blocks, 256 threads.
// ---------------------------------------------------------------------------
__global__ __launch_bounds__(256) void kC(const float* __restrict__ x,
                                          float* __restrict__ out) {
    __shared__ float xs[20][20];
    int tid = threadIdx.x;
    int tx = tid & 15, ty = tid >> 4;
    int tile = blockIdx.x;
    int ty0 = (tile >> 2) << 4, tx0 = (tile & 3) << 4;
    int cg = blockIdx.y, b = blockIdx.z;
    int p = (ty0 + ty) * 64 + tx0 + tx;

    float mk[100];
    #pragma unroll
    for (int k = 0; k < 25; k++)
        #pragma unroll
        for (int s = 0; s < 4; s++)
            mk[k*4+s] = g_mask[(((size_t)b * K2_ + k) * S2_ + s) * HW_ + p];

    for (int ci = 0; ci < 32; ci++) {
        int c = cg * 32 + ci;
        __syncthreads();
        for (int i = tid; i < 400; i += 256) {
            int r = i / 20, cc = i % 20;
            int gy = ty0 + r - 2, gx = tx0 + cc - 2;
            float v = 0.f;
            if ((unsigned)gy < 64u && (unsigned)gx < 64u)
                v = x[((size_t)b * C_ + c) * HW_ + gy * 64 + gx];
            xs[r][cc] = v;
        }
        __syncthreads();
        float a0 = 0.f, a1 = 0.f, a2 = 0.f, a3 = 0.f;
        #pragma unroll
        for (int dy = 0; dy < 5; dy++) {
            #pragma unroll
            for (int dx = 0; dx < 5; dx++) {
                float xv = xs[ty + dy][tx + dx];
                int k = dy * 5 + dx;
                a0 += mk[k*4+0] * xv;
                a1 += mk[k*4+1] * xv;
                a2 += mk[k*4+2] * xv;
                a3 += mk[k*4+3] * xv;
            }
        }
        // s2 -> (s0,s1): output pixel (2i+s0, 2j+s1)
        float* ob = out + (((size_t)b * C_ + c) * 128 + (size_t)(ty0 + ty) * 2) * 128
                        + (size_t)(tx0 + tx) * 2;
        *(float2*)(ob)       = make_float2(a0, a1);
        *(float2*)(ob + 128) = make_float2(a2, a3);
    }
}

// ---------------------------------------------------------------------------
extern "C" void kernel_launch(void* const* d_in, const int* in_sizes, int n_in,
                              void* d_out, int out_size) {
    const float* x      = (const float*)d_in[0];
    const float* w_comp = (const float*)d_in[1];
    const float* gamma_ = (const float*)d_in[2];
    const float* beta_  = (const float*)d_in[3];
    const float* mean_  = (const float*)d_in[4];
    const float* var_   = (const float*)d_in[5];
    const float* w_enc  = (const float*)d_in[6];
    float* out = (float*)d_out;

    kA<<<64, 256>>>(x, w_comp, gamma_, beta_, mean_, var_);
    kB<<<dim3(16, 4, 4), 256>>>(w_enc);
    kC<<<dim3(16, 8, 4), 256>>>(x, out);
}